// round 12
// baseline (speedup 1.0000x reference)
#include <cuda_runtime.h>
#include <cuda_fp16.h>
#include <cstdint>
#include <cstddef>

// Xonv2D: out[b,o,h,w] = sum_{c,kh,kw} x[b,c,h+kh-1,w+kw-1] * W[h,w,o,c,kh,kw] + bias[h,w,o]
// B=4, CIN=COUT=16, K=3, H=W=128. Weights = 151MB streamed once -> HBM-bound.
// Round 12: 6 CTAs/SM x 128 threads, 2-pixel weight chunks (18.4KB), ring-2 TMA.
// 6 independent DRAM streams per SM (was 3). x halo tile fp16 (fp32 accum),
// conflict-free LDS mappings, sout overlaid on x tile, 128-thread barriers.

static constexpr int Hc = 128, Wc = 128;
static constexpr int GROUPS = 8192;                      // 2-pixel groups
static constexpr int FLOATS_PER_PX = 16 * 16 * 9;        // 2304
static constexpr int CHUNK_FLOATS  = 2 * FLOATS_PER_PX;  // 4608
static constexpr int CHUNK_BYTES   = CHUNK_FLOATS * 4;   // 18432
static constexpr int XTILE         = 768;                // halfs (16c*3r*4w*4b)
static constexpr int SMEM_X_OFF    = 2 * CHUNK_BYTES;            // 36864
static constexpr int SMEM_MBAR_OFF = SMEM_X_OFF + XTILE * 2;     // 38400
static constexpr int SMEM_TOTAL    = SMEM_MBAR_OFF + 32;         // 38432 (x6 = 230592 <= 233472)
static constexpr int GRID          = 912;                // 6 CTAs/SM * 152 SMs
static constexpr int NT            = 128;

__device__ __forceinline__ uint32_t smem_u32(const void* p) {
    return (uint32_t)__cvta_generic_to_shared(p);
}
__device__ __forceinline__ void mbar_init(uint32_t a, uint32_t count) {
    asm volatile("mbarrier.init.shared.b64 [%0], %1;" :: "r"(a), "r"(count) : "memory");
}
__device__ __forceinline__ void mbar_expect_tx(uint32_t a, uint32_t bytes) {
    asm volatile("mbarrier.arrive.expect_tx.shared.b64 _, [%0], %1;" :: "r"(a), "r"(bytes) : "memory");
}
__device__ __forceinline__ void tma_bulk_g2s(uint32_t dst, const void* src, uint32_t bytes, uint32_t mbar) {
    asm volatile("cp.async.bulk.shared::cta.global.mbarrier::complete_tx::bytes [%0], [%1], %2, [%3];"
                 :: "r"(dst), "l"(src), "r"(bytes), "r"(mbar) : "memory");
}
__device__ __forceinline__ void mbar_wait(uint32_t a, uint32_t parity) {
    uint32_t done;
    asm volatile(
        "{\n\t.reg .pred p;\n\t"
        "mbarrier.try_wait.parity.acquire.cta.shared::cta.b64 p, [%1], %2;\n\t"
        "selp.b32 %0, 1, 0, p;\n\t}"
        : "=r"(done) : "r"(a), "r"(parity) : "memory");
    while (!done) {
        asm volatile(
            "{\n\t.reg .pred p;\n\t"
            "mbarrier.try_wait.parity.acquire.cta.shared::cta.b64 p, [%1], %2, 0x989680;\n\t"
            "selp.b32 %0, 1, 0, p;\n\t}"
            : "=r"(done) : "r"(a), "r"(parity) : "memory");
    }
}

__global__ void __launch_bounds__(NT, 6)
xonv2d_kernel(const float* __restrict__ x,
              const float* __restrict__ wts,
              const float* __restrict__ bias,
              float* __restrict__ out)
{
    extern __shared__ char smem[];
    float*   swt  = reinterpret_cast<float*>(smem);
    __half*  sxh  = reinterpret_cast<__half*>(smem + SMEM_X_OFF);
    const uint2*  sxu2 = reinterpret_cast<const uint2*>(smem + SMEM_X_OFF);
    float*   sof  = reinterpret_cast<float*>(smem + SMEM_X_OFF);   // epilogue overlay
    float2*  sof2 = reinterpret_cast<float2*>(smem + SMEM_X_OFF);
    const uint32_t mb = smem_u32(smem + SMEM_MBAR_OFF);

    const int t   = threadIdx.x;
    const int bid = blockIdx.x;

    if (t == 0) { mbar_init(mb, 1); mbar_init(mb + 8, 1); }
    __syncthreads();

    // Prologue: weight TMA for chunks bid (slot0), bid+GRID (slot1).
    if (t == 0) {
        mbar_expect_tx(mb, CHUNK_BYTES);
        tma_bulk_g2s(smem_u32(swt), wts + (size_t)bid * CHUNK_FLOATS, CHUNK_BYTES, mb);
        mbar_expect_tx(mb + 8, CHUNK_BYTES);
        tma_bulk_g2s(smem_u32(swt + CHUNK_FLOATS),
                     wts + (size_t)(bid + GRID) * CHUNK_FLOATS, CHUNK_BYTES, mb + 8);
    }

    // Mapping: o0l=bit0, ch=bits1-3 (cin pair), o0h=bit4, o0m=bit5, px=bit6.
    const int o0  = (t & 1) + 2 * ((t >> 4) & 1) + 4 * ((t >> 5) & 1);
    const int ch  = (t >> 1) & 7;
    const int px  = (t >> 6) & 1;
    const int chm = ch & 3;
    const int wbase_f2 = px * 1152 + o0 * 72 + ch * 9;   // float2 units
    const int xbase = 24 * ch;                           // uint2 units, + cc*12 + r*4 + sxv[s]
    const int sxv0 = (px + 0) ^ chm;
    const int sxv1 = (px + 1) ^ chm;
    const int sxv2 = (px + 2) ^ chm;

    // Precomputed x-fill constants (6 elements/thread, loop-invariant).
    int goff[6], sidx[6], pk[6];
    #pragma unroll
    for (int it = 0; it < 6; it++) {
        const int i  = t + it * NT;                      // 0..767
        const int wi = i & 3;
        const int r  = (i >> 2) % 3;
        const int c  = (i / 12) & 15;
        const int b  = i / 192;
        goff[it] = ((b * 16 + c) * Hc + (r - 1)) * Wc + (wi - 1);
        sidx[it] = (c * 12 + r * 4 + (wi ^ ((c >> 1) & 3))) * 4 + b;
        pk[it]   = r | (wi << 4);
    }

    // x prefetch for first chunk.
    float xr[6];
    {
        const int p0 = bid * 2;
        const int h0 = p0 >> 7, w0 = p0 & 127;
        #pragma unroll
        for (int it = 0; it < 6; it++) {
            const int hh = h0 + (pk[it] & 15) - 1;
            const int ww = w0 + (pk[it] >> 4) - 1;
            xr[it] = ((unsigned)hh < 128u && (unsigned)ww < 128u)
                     ? __ldg(x + goff[it] + p0) : 0.0f;
        }
    }
    // bias prefetch: t<64 -> (b=t>>4, o=t&15), two pixels.
    float bs0 = 0.f, bs1 = 0.f;
    if (t < 64) {
        const float* bp = bias + (size_t)bid * 32 + (t & 15);
        bs0 = __ldg(bp); bs1 = __ldg(bp + 16);
    }

    for (int j = 0, gi = bid; gi < GROUPS; j++, gi += GRID) {
        const int slot   = j & 1;
        const int parity = (j >> 1) & 1;

        __syncthreads();   // S1: prev epilogue sof reads done -> x tile writable

        // STS x (fp16) into tile.
        #pragma unroll
        for (int it = 0; it < 6; it++) sxh[sidx[it]] = __float2half_rn(xr[it]);
        __syncthreads();   // S2: x tile ready

        // Prefetch x + bias for next chunk (hidden behind mbar_wait + compute).
        float bn0 = 0.f, bn1 = 0.f;
        {
            const int gn1 = gi + GRID;
            if (gn1 < GROUPS) {
                const int p1 = gn1 * 2;
                const int h0 = p1 >> 7, w0 = p1 & 127;
                #pragma unroll
                for (int it = 0; it < 6; it++) {
                    const int hh = h0 + (pk[it] & 15) - 1;
                    const int ww = w0 + (pk[it] >> 4) - 1;
                    xr[it] = ((unsigned)hh < 128u && (unsigned)ww < 128u)
                             ? __ldg(x + goff[it] + p1) : 0.0f;
                }
                if (t < 64) {
                    const float* bp = bias + (size_t)gn1 * 32 + (t & 15);
                    bn0 = __ldg(bp); bn1 = __ldg(bp + 16);
                }
            }
        }

        mbar_wait(mb + slot * 8, parity);  // weights for chunk gi ready

        const float2* wp = reinterpret_cast<const float2*>(swt + slot * CHUNK_FLOATS) + wbase_f2;

        float a00 = 0.f, a01 = 0.f, a02 = 0.f, a03 = 0.f;
        float a10 = 0.f, a11 = 0.f, a12 = 0.f, a13 = 0.f;

        #pragma unroll
        for (int k = 0; k < 9; k++) {
            const float2 w0v = wp[k];          // cout o0
            const float2 w1v = wp[k + 576];    // cout o0+8
            #pragma unroll
            for (int e = 0; e < 2; e++) {
                const int f   = 2 * k + e;     // 0..17
                const int cc  = f / 9;
                const int tap = f % 9;
                const int r   = tap / 3;
                const int s   = tap % 3;
                const int sxv = (s == 0) ? sxv0 : (s == 1) ? sxv1 : sxv2;
                union { uint2 u; __half2 h[2]; } raw;
                raw.u = sxu2[xbase + cc * 12 + r * 4 + sxv];
                const float2 lo = __half22float2(raw.h[0]);
                const float2 hi = __half22float2(raw.h[1]);
                const float wa = e ? w0v.y : w0v.x;
                const float wb = e ? w1v.y : w1v.x;
                a00 += wa * lo.x;  a01 += wa * lo.y;  a02 += wa * hi.x;  a03 += wa * hi.y;
                a10 += wb * lo.x;  a11 += wb * lo.y;  a12 += wb * hi.x;  a13 += wb * hi.y;
            }
        }

        // Reduce over ch (lane bits 1-3): 3 butterflies.
        #pragma unroll
        for (int m = 2; m <= 8; m <<= 1) {
            a00 += __shfl_xor_sync(0xffffffffu, a00, m);
            a01 += __shfl_xor_sync(0xffffffffu, a01, m);
            a02 += __shfl_xor_sync(0xffffffffu, a02, m);
            a03 += __shfl_xor_sync(0xffffffffu, a03, m);
            a10 += __shfl_xor_sync(0xffffffffu, a10, m);
            a11 += __shfl_xor_sync(0xffffffffu, a11, m);
            a12 += __shfl_xor_sync(0xffffffffu, a12, m);
            a13 += __shfl_xor_sync(0xffffffffu, a13, m);
        }

        __syncthreads();   // S3: all x-tile + weight-slot reads of chunk j done

        // Weight TMA for chunk j+2 into this (now free) slot.
        if (t == 0) {
            const int gn = gi + 2 * GRID;
            if (gn < GROUPS) {
                mbar_expect_tx(mb + slot * 8, CHUNK_BYTES);
                tma_bulk_g2s(smem_u32(swt + slot * CHUNK_FLOATS),
                             wts + (size_t)gn * CHUNK_FLOATS, CHUNK_BYTES, mb + slot * 8);
            }
        }

        // Stage outputs (fp32, overlaid on x tile): sof[(b*16+o)*2 + px].
        if (ch == 0) {
            const int o1 = o0 + 8;
            sof[(0 * 16 + o0) * 2 + px] = a00;
            sof[(1 * 16 + o0) * 2 + px] = a01;
            sof[(2 * 16 + o0) * 2 + px] = a02;
            sof[(3 * 16 + o0) * 2 + px] = a03;
            sof[(0 * 16 + o1) * 2 + px] = a10;
            sof[(1 * 16 + o1) * 2 + px] = a11;
            sof[(2 * 16 + o1) * 2 + px] = a12;
            sof[(3 * 16 + o1) * 2 + px] = a13;
        }
        __syncthreads();   // S4: sout ready

        // Coalesced-ish write: t<64 -> (b=t>>4, o=t&15), float2 over 2 pixels.
        if (t < 64) {
            float2 v = sof2[t];
            v.x += bs0; v.y += bs1;
            *reinterpret_cast<float2*>(out + (size_t)t * (Hc * Wc) + gi * 2) = v;
            bs0 = bn0; bs1 = bn1;
        }
    }
}

extern "C" void kernel_launch(void* const* d_in, const int* in_sizes, int n_in,
                              void* d_out, int out_size) {
    const float* x    = (const float*)d_in[0];
    const float* wts  = (const float*)d_in[1];
    const float* bias = (const float*)d_in[2];
    float* out        = (float*)d_out;

    cudaFuncSetAttribute(xonv2d_kernel, cudaFuncAttributeMaxDynamicSharedMemorySize, SMEM_TOTAL);
    xonv2d_kernel<<<GRID, NT, SMEM_TOTAL>>>(x, wts, bias, out);
}